// round 17
// baseline (speedup 1.0000x reference)
#include <cuda_runtime.h>
#include <cuda_fp16.h>
#include <mma.h>
#include <cstdint>

using namespace nvcuda;

#define NN   50000
#define NPAD 50048
#define EE   640000
#define FIN  128
#define HID  128
#define FOUT 64

struct __align__(8) Edge { int src; float ne; };

// ---------------- device scratch ----------------
__device__ __align__(16) float  g_xres[NPAD * HID];     // x @ Wres (fp32)
__device__ __align__(16) __half g_p16[NPAD * HID];      // P = H @ W (fp16)
__device__ __align__(16) __half g_a[NPAD * HID];        // activations (fp16)
__device__ float g_dinv[NN];
__device__ float g_nself[NN];
__device__ int   g_deg[NN];
__device__ int   g_offs[NN];
__device__ int   g_cursor[NN];
__device__ int   g_bsum[256];
__device__ Edge  g_csr[EE];
// fp16 weights, [128,FO] row-major, 5 slots
__device__ __align__(256) __half g_wh[5 * 16384];

__device__ __forceinline__ float* pick_dst(int sel, float* ext) {
    if (sel == 3) return g_xres;
    return ext;
}

// ---------------- cp.async helpers ----------------
__device__ __forceinline__ void cp_async16(uint32_t smem_addr, const void* gptr) {
    asm volatile("cp.async.cg.shared.global [%0], [%1], 16;"
                 :: "r"(smem_addr), "l"(gptr));
}
#define CP_COMMIT() asm volatile("cp.async.commit_group;" ::: "memory")
#define CP_WAIT0()  asm volatile("cp.async.wait_group 0;" ::: "memory")

__device__ __forceinline__ uint32_t pack_h2(__half a, __half b) {
    __half2 p = __halves2half2(a, b);
    return *(uint32_t*)&p;
}

// ---------------- graph preprocessing ----------------
__global__ void k_zero_deg(int n) {
    int i = blockIdx.x * blockDim.x + threadIdx.x;
    if (i < n) g_deg[i] = 0;
}
__global__ void k_count(const int* __restrict__ ei, int e, int n) {
    int i = blockIdx.x * blockDim.x + threadIdx.x;
    if (i < e) {
        int dst = ei[e + i];
        if (dst >= 0 && dst < n) atomicAdd(&g_deg[dst], 1);
    }
}
// block scan + norm fused
__global__ __launch_bounds__(256) void k_scan_blk(int n) {
    int gid  = blockIdx.x * 256 + threadIdx.x;
    int lane = threadIdx.x & 31;
    int wid  = threadIdx.x >> 5;
    int v = (gid < n) ? g_deg[gid] : 0;
    if (gid < n) {
        float dd = (float)v + 1.0f;
        g_dinv[gid]  = rsqrtf(dd);
        g_nself[gid] = 1.0f / dd;
    }
    int x = v;
#pragma unroll
    for (int o = 1; o < 32; o <<= 1) {
        int y = __shfl_up_sync(0xffffffffu, x, o);
        if (lane >= o) x += y;
    }
    __shared__ int wsum[8];
    if (lane == 31) wsum[wid] = x;
    __syncthreads();
    if (wid == 0) {
        int s = (lane < 8) ? wsum[lane] : 0;
#pragma unroll
        for (int o = 1; o < 8; o <<= 1) {
            int y = __shfl_up_sync(0xffffffffu, s, o);
            if (lane >= o) s += y;
        }
        if (lane < 8) wsum[lane] = s;
    }
    __syncthreads();
    int incl = x + (wid > 0 ? wsum[wid - 1] : 0);
    if (gid < n) g_offs[gid] = incl - v;
    if (threadIdx.x == 255) g_bsum[blockIdx.x] = incl;
}
__global__ __launch_bounds__(256) void k_scan_top(int nb) {
    int tid  = threadIdx.x;
    int lane = tid & 31;
    int wid  = tid >> 5;
    int v = (tid < nb) ? g_bsum[tid] : 0;
    int x = v;
#pragma unroll
    for (int o = 1; o < 32; o <<= 1) {
        int y = __shfl_up_sync(0xffffffffu, x, o);
        if (lane >= o) x += y;
    }
    __shared__ int wsum[8];
    if (lane == 31) wsum[wid] = x;
    __syncthreads();
    if (wid == 0) {
        int s = (lane < 8) ? wsum[lane] : 0;
#pragma unroll
        for (int o = 1; o < 8; o <<= 1) {
            int y = __shfl_up_sync(0xffffffffu, s, o);
            if (lane >= o) s += y;
        }
        if (lane < 8) wsum[lane] = s;
    }
    __syncthreads();
    int incl = x + (wid > 0 ? wsum[wid - 1] : 0);
    if (tid < nb) g_bsum[tid] = incl - v;
}
__global__ __launch_bounds__(256) void k_scan_add(int n) {
    int gid = blockIdx.x * 256 + threadIdx.x;
    if (gid < n) {
        int o = g_offs[gid] + g_bsum[blockIdx.x];
        g_offs[gid]   = o;
        g_cursor[gid] = o;
    }
}
__global__ void k_fill(const int* __restrict__ ei, int e, int n) {
    int i = blockIdx.x * blockDim.x + threadIdx.x;
    if (i < e) {
        int src = ei[i];
        int dst = ei[e + i];
        if (src < 0 || src >= n || dst < 0 || dst >= n) return;
        int pos = atomicAdd(&g_cursor[dst], 1);
        if (pos >= 0 && pos < EE) {
            Edge ed;
            ed.src = src;
            ed.ne  = g_dinv[src] * g_dinv[dst];
            g_csr[pos] = ed;
        }
    }
}

// ---------------- weight prep: fp32 -> fp16 ----------------
template <int FO>
__global__ void k_wprep(const float* __restrict__ W, int slot) {
    int i = blockIdx.x * blockDim.x + threadIdx.x;
    if (i >= 128 * FO) return;
    g_wh[slot * 16384 + i] = __float2half(W[i]);
}

// ---------------- activation prep: fp32 -> fp16 (x only) ----------------
__global__ __launch_bounds__(256) void k_aconv(const float* __restrict__ X, int n) {
    int i = blockIdx.x * 256 + threadIdx.x;          // float4 index
    if (i * 4 >= NPAD * HID) return;
    float4 v = make_float4(0.f, 0.f, 0.f, 0.f);
    if (i * 4 < n * HID) v = ((const float4*)X)[i];
    uint2 hv = make_uint2(pack_h2(__float2half(v.x), __float2half(v.y)),
                          pack_h2(__float2half(v.z), __float2half(v.w)));
    *(uint2*)(g_a + (size_t)i * 4) = hv;
}

// ---------------- wmma fp16 GEMM (unchanged from R16) ----------------
template <int FO, int MODE>
__global__ __launch_bounds__(256, 2) void k_gemm_wmma(
    int wslot, const float* __restrict__ bias, float* Yext, int ysel, int n)
{
    float* __restrict__ Y = pick_dst(ysel, Yext);
    const __half* __restrict__ Wh = g_wh + wslot * 16384;

    constexpr int NT = FO / 16;
    constexpr int AS = 40;
    constexpr int BS = FO + 8;

    __shared__ __align__(256) __half sA[2][128 * AS];
    __shared__ __align__(256) __half sB[2][32 * BS];

    int tid  = threadIdx.x;
    int wid  = tid >> 5;
    int lane = tid & 31;
    int row0 = blockIdx.x * 128;
    int wrow = row0 + wid * 16;

    auto issue_stage = [&](int kc, int st) {
#pragma unroll
        for (int i = 0; i < 2; i++) {
            int idx = tid + i * 256;
            int ar  = idx >> 2;
            int ac8 = (idx & 3) * 8;
            size_t goff = (size_t)(row0 + ar) * HID + kc * 32 + ac8;
            uint32_t sa = (uint32_t)__cvta_generic_to_shared(&sA[st][ar * AS + ac8]);
            cp_async16(sa, g_a + goff);
        }
        if (FO == 128) {
#pragma unroll
            for (int i = 0; i < 2; i++) {
                int idx = tid + i * 256;
                int br  = idx >> 4;
                int bc8 = (idx & 15) * 8;
                size_t woff = (size_t)(kc * 32 + br) * FO + bc8;
                uint32_t sb = (uint32_t)__cvta_generic_to_shared(&sB[st][br * BS + bc8]);
                cp_async16(sb, Wh + woff);
            }
        } else {
            int br  = tid >> 3;
            int bc8 = (tid & 7) * 8;
            size_t woff = (size_t)(kc * 32 + br) * FO + bc8;
            uint32_t sb = (uint32_t)__cvta_generic_to_shared(&sB[st][br * BS + bc8]);
            cp_async16(sb, Wh + woff);
        }
        CP_COMMIT();
    };

    wmma::fragment<wmma::accumulator, 16, 16, 16, float> acc[NT];
#pragma unroll
    for (int i = 0; i < NT; i++) wmma::fill_fragment(acc[i], 0.0f);

    issue_stage(0, 0);

#pragma unroll
    for (int kc = 0; kc < 4; kc++) {
        int st = kc & 1;
        CP_WAIT0();
        __syncthreads();
        if (kc < 3) issue_stage(kc + 1, st ^ 1);

#pragma unroll
        for (int ks = 0; ks < 2; ks++) {
            wmma::fragment<wmma::matrix_a, 16, 16, 16, __half, wmma::row_major> fa;
            wmma::load_matrix_sync(fa, &sA[st][(wid * 16) * AS + ks * 16], AS);
#pragma unroll
            for (int nt = 0; nt < NT; nt++) {
                wmma::fragment<wmma::matrix_b, 16, 16, 16, __half, wmma::row_major> fb;
                wmma::load_matrix_sync(fb, &sB[st][(ks * 16) * BS + nt * 16], BS);
                wmma::mma_sync(acc[nt], fa, fb, acc[nt]);
            }
        }
    }
    __syncthreads();

    if constexpr (MODE == 0) {
#pragma unroll
        for (int nt = 0; nt < NT; nt++)
            wmma::store_matrix_sync(Y + (size_t)wrow * FO + nt * 16, acc[nt],
                                    FO, wmma::mem_row_major);
    } else if constexpr (MODE == 1) {
        float* stage = (float*)sA + wid * 320;
#pragma unroll
        for (int nt = 0; nt < NT; nt++) {
            wmma::store_matrix_sync(stage, acc[nt], 20, wmma::mem_row_major);
            __syncwarp();
#pragma unroll
            for (int j = 0; j < 4; j++) {
                int idx = lane + j * 32;
                int r  = idx >> 3;
                int c2 = idx & 7;
                __half2 h = __floats2half2_rn(stage[r * 20 + c2 * 2],
                                              stage[r * 20 + c2 * 2 + 1]);
                *(__half2*)(g_p16 + (size_t)(wrow + r) * FO + nt * 16 + c2 * 2) = h;
            }
            __syncwarp();
        }
    } else {
        float* stage = (float*)sA + wid * 320;
#pragma unroll
        for (int nt = 0; nt < NT; nt++) {
            wmma::store_matrix_sync(stage, acc[nt], 20, wmma::mem_row_major);
            __syncwarp();
#pragma unroll
            for (int j = 0; j < 8; j++) {
                int idx = lane + j * 32;
                int r = idx >> 4;
                int c = idx & 15;
                int grow = wrow + r;
                if (grow < n) {
                    float b = bias ? bias[nt * 16 + c] : 0.0f;
                    Y[(size_t)grow * FO + nt * 16 + c] = stage[r * 20 + c] + b;
                }
            }
            __syncwarp();
        }
    }
}

// ---- fused GCN aggregation: packed CSR, unroll-8 with index prefetch ----
__global__ __launch_bounds__(256) void k_gather(
    int rsel, const float* __restrict__ bias,
    const float* __restrict__ bias2, int n)
{
    const float* __restrict__ res = (rsel == 3) ? g_xres : nullptr;

    int warp = (blockIdx.x * blockDim.x + threadIdx.x) >> 5;
    int lane = threadIdx.x & 31;
    if (warp >= n) return;
    int node = warp;

    float ns = g_nself[node];
    uint2 sv = *(const uint2*)(g_p16 + (size_t)node * 128 + lane * 4);
    float2 s01 = __half22float2(*(__half2*)&sv.x);
    float2 s23 = __half22float2(*(__half2*)&sv.y);
    float a0x = s01.x * ns, a0y = s01.y * ns, a0z = s23.x * ns, a0w = s23.y * ns;
    float a1x = 0.f, a1y = 0.f, a1z = 0.f, a1w = 0.f;
    float a2x = 0.f, a2y = 0.f, a2z = 0.f, a2w = 0.f;
    float a3x = 0.f, a3y = 0.f, a3z = 0.f, a3w = 0.f;

    int start = g_offs[node];
    int d     = g_deg[node];
    const Edge* ep = g_csr + start;
    int nb = d >> 3;                     // full 8-edge batches

    Edge nxt[8];
    if (nb > 0) {
#pragma unroll
        for (int j = 0; j < 8; j++) nxt[j] = ep[j];
    }
    for (int b = 0; b < nb; b++) {
        Edge cur[8];
#pragma unroll
        for (int j = 0; j < 8; j++) cur[j] = nxt[j];
        if (b + 1 < nb) {
#pragma unroll
            for (int j = 0; j < 8; j++) nxt[j] = ep[(b + 1) * 8 + j];
        }
        uint2 v[8];
#pragma unroll
        for (int j = 0; j < 8; j++)
            v[j] = *(const uint2*)(g_p16 + (size_t)cur[j].src * 128 + lane * 4);
#pragma unroll
        for (int j = 0; j < 8; j++) {
            float2 p01 = __half22float2(*(__half2*)&v[j].x);
            float2 p23 = __half22float2(*(__half2*)&v[j].y);
            float ne = cur[j].ne;
            switch (j & 3) {
            case 0: a0x += p01.x * ne; a0y += p01.y * ne; a0z += p23.x * ne; a0w += p23.y * ne; break;
            case 1: a1x += p01.x * ne; a1y += p01.y * ne; a1z += p23.x * ne; a1w += p23.y * ne; break;
            case 2: a2x += p01.x * ne; a2y += p01.y * ne; a2z += p23.x * ne; a2w += p23.y * ne; break;
            default: a3x += p01.x * ne; a3y += p01.y * ne; a3z += p23.x * ne; a3w += p23.y * ne; break;
            }
        }
    }
    for (int i = nb * 8; i < d; i++) {
        Edge ed = ep[i];
        uint2 v = *(const uint2*)(g_p16 + (size_t)ed.src * 128 + lane * 4);
        float2 p01 = __half22float2(*(__half2*)&v.x);
        float2 p23 = __half22float2(*(__half2*)&v.y);
        a0x += p01.x * ed.ne; a0y += p01.y * ed.ne;
        a0z += p23.x * ed.ne; a0w += p23.y * ed.ne;
    }
    float ax = a0x + a1x + a2x + a3x;
    float ay = a0y + a1y + a2y + a3y;
    float az = a0z + a1z + a2z + a3z;
    float aw = a0w + a1w + a2w + a3w;

    float4 b4 = ((const float4*)bias)[lane];
    ax += b4.x; ay += b4.y; az += b4.z; aw += b4.w;
    if (bias2) {
        float4 b2 = ((const float4*)bias2)[lane];
        ax += b2.x; ay += b2.y; az += b2.z; aw += b2.w;
    }
    if (res) {
        float4 r4 = ((const float4*)(res + (size_t)node * 128))[lane];
        ax += r4.x; ay += r4.y; az += r4.z; aw += r4.w;
    }
    ax = fmaxf(ax, 0.f);
    ay = fmaxf(ay, 0.f);
    az = fmaxf(az, 0.f);
    aw = fmaxf(aw, 0.f);

    uint2 hv = make_uint2(pack_h2(__float2half(ax), __float2half(ay)),
                          pack_h2(__float2half(az), __float2half(aw)));
    *(uint2*)(g_a + (size_t)node * 128 + lane * 4) = hv;
}

// ---------------- launch ----------------
extern "C" void kernel_launch(void* const* d_in, const int* in_sizes, int n_in,
                              void* d_out, int out_size)
{
    const float* x    = (const float*)d_in[0];
    const int*   ei   = (const int*)d_in[1];
    const float* W1   = (const float*)d_in[2];
    const float* b1   = (const float*)d_in[3];
    const float* W2   = (const float*)d_in[4];
    const float* b2   = (const float*)d_in[5];
    const float* W3   = (const float*)d_in[6];
    const float* b3   = (const float*)d_in[7];
    const float* Wres = (const float*)d_in[8];
    const float* bres = (const float*)d_in[9];
    const float* Wlin = (const float*)d_in[10];
    const float* blin = (const float*)d_in[11];
    float* out = (float*)d_out;

    int n = in_sizes[0] / FIN;
    int e = in_sizes[1] / 2;

    int nb256  = (n + 255) / 256;
    int eb256  = (e + 255) / 256;
    int gemmb  = (n + 127) / 128;
    int gathb  = (n + 7) / 8;
    int aconvb = (NPAD * HID / 4 + 255) / 256;

    // ---- prep, then xres GEMM early ----
    k_wprep<128><<<64, 256>>>(Wres, 3);
    k_wprep<128><<<64, 256>>>(W1,   0);
    k_aconv<<<aconvb, 256>>>(x, n);
    k_gemm_wmma<128, 0><<<gemmb, 256>>>(3, nullptr, nullptr, 3, n);
    k_gemm_wmma<128, 1><<<gemmb, 256>>>(0, nullptr, nullptr, 0, n);
    k_wprep<128><<<64, 256>>>(W2,   1);
    k_wprep<128><<<64, 256>>>(W3,   2);
    k_wprep<64><<<32, 256>>>(Wlin,  4);

    // graph preprocessing (norm fused into scan_blk)
    k_zero_deg<<<nb256, 256>>>(n);
    k_count<<<eb256, 256>>>(ei, e, n);
    k_scan_blk<<<nb256, 256>>>(n);
    k_scan_top<<<1, 256>>>(nb256);
    k_scan_add<<<nb256, 256>>>(n);
    k_fill<<<eb256, 256>>>(ei, e, n);

    // layer 1 aggregation -> g_a
    k_gather<<<gathb, 256>>>(3, b1, bres, n);

    // layer 2
    k_gemm_wmma<128, 1><<<gemmb, 256>>>(1, nullptr, nullptr, 0, n);
    k_gather<<<gathb, 256>>>(0, b2, nullptr, n);

    // layer 3
    k_gemm_wmma<128, 1><<<gemmb, 256>>>(2, nullptr, nullptr, 0, n);
    k_gather<<<gathb, 256>>>(0, b3, nullptr, n);

    // output projection (guarded epilogue + blin)
    k_gemm_wmma<64, 2><<<gemmb, 256>>>(4, blin, out, 0, n);
}